// round 12
// baseline (speedup 1.0000x reference)
#include <cuda_runtime.h>
#include <cuda_fp16.h>
#include <math.h>
#include <stdint.h>

// Problem constants (fixed by the dataset)
#define NN      10000        // nodes
#define EE      160000       // edges (before self loops)
#define IND     512
#define HID     128
#define HEADS   8
#define D1      (HEADS*HID)  // 1024
#define EMB     256

// ---------------- scratch (static __device__, no allocation) ----------------
__device__ __align__(16) __half g_xh  [NN * IND];   // x in fp16
__device__ __align__(16) __half g_w1t [IND * D1];   // W1^T  [n][k] fp16
__device__ __align__(16) __half g_w2t [D1 * EMB];   // W2^T  [n][k] fp16
__device__ __align__(16) __half g_h1h [NN * D1];    // layer1 features (fp16)
__device__ __align__(16) __half g_h1eh[NN * D1];    // layer1 aggr+ELU out (fp16)
__device__ __align__(16) __half g_h2h [NN * EMB];   // layer2 features (fp16)
#define ALPHA_TOT (2*NN*HEADS + 2*NN)
__device__ float g_alpha[ALPHA_TOT];  // [as1 | ad1 | as2 | ad2]
__device__ int   g_cnt[NN];
__device__ int   g_ptr[NN + 1];
__device__ int   g_cur[NN];
__device__ int   g_csr[EE];

// ---------------- helpers ----------------
__device__ __forceinline__ void mma_f16(float d[4],
        uint32_t a0, uint32_t a1, uint32_t a2, uint32_t a3,
        uint32_t b0, uint32_t b1) {
    asm volatile(
        "mma.sync.aligned.m16n8k16.row.col.f32.f16.f16.f32 "
        "{%0,%1,%2,%3}, {%4,%5,%6,%7}, {%8,%9}, {%0,%1,%2,%3};"
        : "+f"(d[0]), "+f"(d[1]), "+f"(d[2]), "+f"(d[3])
        : "r"(a0), "r"(a1), "r"(a2), "r"(a3), "r"(b0), "r"(b1));
}

__device__ __forceinline__ void cpAsync16(uint32_t dst_smem, const void* src, bool valid) {
    int sz = valid ? 16 : 0;
    asm volatile("cp.async.cg.shared.global [%0], [%1], 16, %2;"
                 :: "r"(dst_smem), "l"(src), "r"(sz));
}

__device__ __forceinline__ float lrelu(float v) { return v > 0.f ? v : 0.2f * v; }
__device__ __forceinline__ float safexp(float v) { return __expf(fminf(v, 80.f)); }

// ================= prep: fp32 -> fp16 convert / transpose =================
__global__ void f2h_kernel(const float* __restrict__ in, __half* __restrict__ out, int n4) {
    int i = blockIdx.x * blockDim.x + threadIdx.x;
    if (i >= n4) return;
    float4 v = ((const float4*)in)[i];
    __half2 h0 = __floats2half2_rn(v.x, v.y);
    __half2 h1 = __floats2half2_rn(v.z, v.w);
    ((uint2*)out)[i] = make_uint2(*(uint32_t*)&h0, *(uint32_t*)&h1);
}

__global__ void wt_kernel(const float* __restrict__ W, __half* __restrict__ Wt,
                          int K, int N) {
    int idx = blockIdx.x * blockDim.x + threadIdx.x;
    if (idx >= K * N) return;
    int k = idx / N, n = idx % N;
    Wt[(size_t)n * K + k] = __float2half(W[idx]);
}

// ================= init: zero alphas + cnt (side stream) =================
__global__ void init_zero_kernel(float* alpha, int na, int* cnt, int nc) {
    int i = blockIdx.x * blockDim.x + threadIdx.x;
    if (i < na) alpha[i] = 0.f;
    if (i < nc) cnt[i] = 0;
}

// ================= CSR build =================
__global__ void csr_count_kernel(const int* __restrict__ ei, int E, int* cnt) {
    int e = blockIdx.x * blockDim.x + threadIdx.x;
    if (e < E) atomicAdd(&cnt[ei[E + e]], 1);
}

__global__ void csr_scan_kernel(const int* __restrict__ cnt, int* __restrict__ ptr,
                                int* __restrict__ cur, int N) {
    __shared__ int sm[1024];
    __shared__ int carry_s;
    int tid = threadIdx.x;
    if (tid == 0) { carry_s = 0; ptr[0] = 0; }
    __syncthreads();
    for (int base = 0; base < N; base += 1024) {
        int i = base + tid;
        int v = (i < N) ? cnt[i] : 0;
        sm[tid] = v;
        __syncthreads();
        #pragma unroll
        for (int off = 1; off < 1024; off <<= 1) {
            int t = (tid >= off) ? sm[tid - off] : 0;
            __syncthreads();
            sm[tid] += t;
            __syncthreads();
        }
        int carry = carry_s;
        if (i < N) {
            ptr[i + 1] = carry + sm[tid];
            cur[i]     = carry + sm[tid] - v;
        }
        __syncthreads();
        if (tid == 1023) carry_s = carry + sm[1023];
        __syncthreads();
    }
}

__global__ void csr_scatter_kernel(const int* __restrict__ ei, int E,
                                   int* cur, int* __restrict__ csr) {
    int e = blockIdx.x * blockDim.x + threadIdx.x;
    if (e >= E) return;
    int src = ei[e], dst = ei[E + e];
    int pos = atomicAdd(&cur[dst], 1);
    csr[pos] = src;
}

// ================= fp16 HMMA GEMM (m16n8k16), fused alpha epilogue ==========
#define KT    32
#define STRH  40
#define GEMM_SMEM ((2*128*STRH + 2*128*STRH) * 2)   // 40960 bytes

__global__ __launch_bounds__(256, 2) void hgemm_kernel(
        const __half* __restrict__ A, const __half* __restrict__ Bt,
        __half* __restrict__ Ch, int M, int N, int K,
        float* as_, float* ad_,
        const float* __restrict__ avs, const float* __restrict__ avd, int HC) {
    extern __shared__ __half smh[];
    __half* AsP[2] = { smh, smh + 128 * STRH };
    __half* BsP[2] = { smh + 2 * 128 * STRH, smh + 3 * 128 * STRH };
    uint32_t asb[2], bsb[2];
    #pragma unroll
    for (int s = 0; s < 2; s++) {
        asb[s] = (uint32_t)__cvta_generic_to_shared(AsP[s]);
        bsb[s] = (uint32_t)__cvta_generic_to_shared(BsP[s]);
    }

    const int tid   = threadIdx.x;
    const int lane  = tid & 31;
    const int w     = tid >> 5;
    const int warp_m = (w & 1) * 64;
    const int warp_n = (w >> 1) * 32;
    const int lq = lane >> 2;
    const int lr = lane & 3;

    const int row0 = blockIdx.y * 128;
    const int col0 = blockIdx.x * 128;
    const int T = K / KT;

    float acc[4][4][4];
    #pragma unroll
    for (int mf = 0; mf < 4; mf++)
        #pragma unroll
        for (int nf = 0; nf < 4; nf++)
            #pragma unroll
            for (int c = 0; c < 4; c++) acc[mf][nf][c] = 0.f;

    const int ldR = tid >> 2;
    const int ldC = (tid & 3) * 8;

    auto loadTile = [&](int t, int s) {
        const int k0 = t * KT;
        #pragma unroll
        for (int i = 0; i < 2; i++) {
            int m = ldR + 64 * i;
            int r = row0 + m;
            bool ok = (r < M);
            const __half* src = A + (size_t)(ok ? r : 0) * K + k0 + ldC;
            cpAsync16(asb[s] + (m * STRH + ldC) * 2, src, ok);
        }
        #pragma unroll
        for (int i = 0; i < 2; i++) {
            int n = ldR + 64 * i;
            const __half* src = Bt + (size_t)(col0 + n) * K + k0 + ldC;
            cpAsync16(bsb[s] + (n * STRH + ldC) * 2, src, true);
        }
        asm volatile("cp.async.commit_group;");
    };

    loadTile(0, 0);

    for (int t = 0; t < T; t++) {
        const int s = t & 1;
        if (t + 1 < T) {
            loadTile(t + 1, 1 - s);
            asm volatile("cp.async.wait_group 1;");
        } else {
            asm volatile("cp.async.wait_group 0;");
        }
        __syncthreads();

        const __half* as = AsP[s];
        const __half* bs = BsP[s];
        #pragma unroll
        for (int ks = 0; ks < 2; ks++) {
            const int kc = ks * 16;
            uint32_t af[4][4], bf[4][2];
            #pragma unroll
            for (int mf = 0; mf < 4; mf++) {
                const __half* p = as + (warp_m + mf * 16 + lq) * STRH + kc + 2 * lr;
                af[mf][0] = *(const uint32_t*)p;
                af[mf][1] = *(const uint32_t*)(p + 8 * STRH);
                af[mf][2] = *(const uint32_t*)(p + 8);
                af[mf][3] = *(const uint32_t*)(p + 8 * STRH + 8);
            }
            #pragma unroll
            for (int nf = 0; nf < 4; nf++) {
                const __half* q = bs + (warp_n + nf * 8 + lq) * STRH + kc + 2 * lr;
                bf[nf][0] = *(const uint32_t*)q;
                bf[nf][1] = *(const uint32_t*)(q + 8);
            }
            #pragma unroll
            for (int mf = 0; mf < 4; mf++)
                #pragma unroll
                for (int nf = 0; nf < 4; nf++)
                    mma_f16(acc[mf][nf], af[mf][0], af[mf][1], af[mf][2], af[mf][3],
                            bf[nf][0], bf[nf][1]);
        }
        __syncthreads();
    }

    #pragma unroll
    for (int mf = 0; mf < 4; mf++) {
        int r = row0 + warp_m + mf * 16 + lq;
        #pragma unroll
        for (int nf = 0; nf < 4; nf++) {
            int c = col0 + warp_n + nf * 8 + lr * 2;
            if (r < M)
                *(__half2*)&Ch[(size_t)r * N + c] =
                    __floats2half2_rn(acc[mf][nf][0], acc[mf][nf][1]);
            if (r + 8 < M)
                *(__half2*)&Ch[(size_t)(r + 8) * N + c] =
                    __floats2half2_rn(acc[mf][nf][2], acc[mf][nf][3]);
        }
    }

    // fused alpha epilogue
    {
        const int H    = N / HC;
        const int head = col0 / HC;
        float vs[4][2], vd[4][2];
        #pragma unroll
        for (int nf = 0; nf < 4; nf++) {
            int c = col0 + warp_n + nf * 8 + lr * 2;
            vs[nf][0] = avs[c];     vs[nf][1] = avs[c + 1];
            vd[nf][0] = avd[c];     vd[nf][1] = avd[c + 1];
        }
        #pragma unroll
        for (int mf = 0; mf < 4; mf++) {
            float s1a = 0.f, s2a = 0.f, s1b = 0.f, s2b = 0.f;
            #pragma unroll
            for (int nf = 0; nf < 4; nf++) {
                s1a += acc[mf][nf][0] * vs[nf][0] + acc[mf][nf][1] * vs[nf][1];
                s2a += acc[mf][nf][0] * vd[nf][0] + acc[mf][nf][1] * vd[nf][1];
                s1b += acc[mf][nf][2] * vs[nf][0] + acc[mf][nf][3] * vs[nf][1];
                s2b += acc[mf][nf][2] * vd[nf][0] + acc[mf][nf][3] * vd[nf][1];
            }
            #pragma unroll
            for (int off = 1; off < 4; off <<= 1) {
                s1a += __shfl_xor_sync(0xFFFFFFFFu, s1a, off);
                s2a += __shfl_xor_sync(0xFFFFFFFFu, s2a, off);
                s1b += __shfl_xor_sync(0xFFFFFFFFu, s1b, off);
                s2b += __shfl_xor_sync(0xFFFFFFFFu, s2b, off);
            }
            if (lr == 0) {
                int r = row0 + warp_m + mf * 16 + lq;
                if (r < M) {
                    atomicAdd(&as_[r * H + head], s1a);
                    atomicAdd(&ad_[r * H + head], s2a);
                }
                if (r + 8 < M) {
                    atomicAdd(&as_[(r + 8) * H + head], s1b);
                    atomicAdd(&ad_[(r + 8) * H + head], s2b);
                }
            }
        }
    }
}

// ================= layer-1 fused aggregation: 2 warps per head =============
// 512 threads/CTA = 16 warps: warp w -> head (w&7), half (w>>3). Each warp
// covers half the node's edge list (halves the serial dependent chain);
// partials combined through smem.
__global__ __launch_bounds__(512) void aggr1_kernel(
        const int* __restrict__ ptr, const int* __restrict__ csr,
        const float* __restrict__ as_, const float* __restrict__ ad_,
        const __half* __restrict__ h1h, const float* __restrict__ b1,
        __half* __restrict__ h1eh) {
    __shared__ float s_acc[HEADS][HID + 4];
    __shared__ float s_den[HEADS];

    const int n    = blockIdx.x;
    const int w    = threadIdx.x >> 5;
    const int lane = threadIdx.x & 31;
    const int hh   = w & 7;
    const int half = w >> 3;
    const int beg = ptr[n], end = ptr[n + 1];
    const int mid = beg + ((end - beg + 1) >> 1);
    const int lo = half ? mid : beg;
    const int hi = half ? end : mid;
    const float adv = ad_[n * HEADS + hh];
    const int ch = hh * HID + lane * 4;

    float4 acc = make_float4(0.f, 0.f, 0.f, 0.f);
    float den = 0.f;
    if (half == 0) {   // self loop
        float ex = safexp(lrelu(as_[n * HEADS + hh] + adv));
        den = ex;
        uint2 u = *(const uint2*)&h1h[(size_t)n * D1 + ch];
        float2 f0 = __half22float2(*(__half2*)&u.x);
        float2 f1 = __half22float2(*(__half2*)&u.y);
        acc.x = ex * f0.x; acc.y = ex * f0.y; acc.z = ex * f1.x; acc.w = ex * f1.y;
    }

    // 2-wide pipelined loop over [lo,hi)
    int i = lo;
    int   s0 = 0, s1 = 0;
    float a0 = 0.f, a1 = 0.f;
    if (i     < hi) { s0 = csr[i];     a0 = as_[s0 * HEADS + hh]; }
    if (i + 1 < hi) { s1 = csr[i + 1]; a1 = as_[s1 * HEADS + hh]; }
    for (; i + 2 <= hi; i += 2) {
        int   s2 = 0, s3 = 0;
        float a2 = 0.f, a3 = 0.f;
        if (i + 2 < hi) { s2 = csr[i + 2]; a2 = as_[s2 * HEADS + hh]; }
        if (i + 3 < hi) { s3 = csr[i + 3]; a3 = as_[s3 * HEADS + hh]; }
        uint2 u0 = *(const uint2*)&h1h[(size_t)s0 * D1 + ch];
        uint2 u1 = *(const uint2*)&h1h[(size_t)s1 * D1 + ch];
        float e0 = safexp(lrelu(a0 + adv));
        float e1 = safexp(lrelu(a1 + adv));
        den += e0 + e1;
        float2 p0 = __half22float2(*(__half2*)&u0.x);
        float2 p1 = __half22float2(*(__half2*)&u0.y);
        float2 q0 = __half22float2(*(__half2*)&u1.x);
        float2 q1 = __half22float2(*(__half2*)&u1.y);
        acc.x += e0 * p0.x + e1 * q0.x;
        acc.y += e0 * p0.y + e1 * q0.y;
        acc.z += e0 * p1.x + e1 * q1.x;
        acc.w += e0 * p1.y + e1 * q1.y;
        s0 = s2; a0 = a2; s1 = s3; a1 = a3;
    }
    if (i < hi) {
        uint2 u0 = *(const uint2*)&h1h[(size_t)s0 * D1 + ch];
        float e0 = safexp(lrelu(a0 + adv));
        den += e0;
        float2 p0 = __half22float2(*(__half2*)&u0.x);
        float2 p1 = __half22float2(*(__half2*)&u0.y);
        acc.x += e0 * p0.x; acc.y += e0 * p0.y;
        acc.z += e0 * p1.x; acc.w += e0 * p1.y;
    }

    // combine halves through smem
    if (half == 1) {
        *(float4*)&s_acc[hh][lane * 4] = acc;
        if (lane == 0) s_den[hh] = den;
    }
    __syncthreads();
    if (half == 0) {
        float4 o2 = *(const float4*)&s_acc[hh][lane * 4];
        acc.x += o2.x; acc.y += o2.y; acc.z += o2.z; acc.w += o2.w;
        den += s_den[hh];

        const float inv = 1.f / den;
        float x0 = acc.x * inv + b1[ch + 0];
        float x1 = acc.y * inv + b1[ch + 1];
        float x2 = acc.z * inv + b1[ch + 2];
        float x3 = acc.w * inv + b1[ch + 3];
        x0 = x0 > 0.f ? x0 : expm1f(x0);
        x1 = x1 > 0.f ? x1 : expm1f(x1);
        x2 = x2 > 0.f ? x2 : expm1f(x2);
        x3 = x3 > 0.f ? x3 : expm1f(x3);
        __half2 ho0 = __floats2half2_rn(x0, x1);
        __half2 ho1 = __floats2half2_rn(x2, x3);
        *(uint2*)&h1eh[(size_t)n * D1 + ch] =
            make_uint2(*(uint32_t*)&ho0, *(uint32_t*)&ho1);
    }
}

// ================= layer-2 fused aggregation (fp16 gather, 2-wide MLP) ======
__global__ __launch_bounds__(256) void aggr2_kernel(
        const int* __restrict__ ptr, const int* __restrict__ csr,
        const float* __restrict__ as_, const float* __restrict__ ad_,
        const __half* __restrict__ h2h, const float* __restrict__ b2,
        float* __restrict__ out, int N) {
    const int n    = (blockIdx.x * blockDim.x + threadIdx.x) >> 5;
    const int lane = threadIdx.x & 31;
    if (n >= N) return;
    const int beg = ptr[n], end = ptr[n + 1];
    const float adv = ad_[n];
    const int c0 = lane * 8;

    float a[8];
    float den;
    {   // self loop
        float ex = safexp(lrelu(as_[n] + adv));
        den = ex;
        uint4 u = *(const uint4*)&h2h[(size_t)n * EMB + c0];
        float2 f0 = __half22float2(*(__half2*)&u.x);
        float2 f1 = __half22float2(*(__half2*)&u.y);
        float2 f2 = __half22float2(*(__half2*)&u.z);
        float2 f3 = __half22float2(*(__half2*)&u.w);
        a[0] = ex * f0.x; a[1] = ex * f0.y; a[2] = ex * f1.x; a[3] = ex * f1.y;
        a[4] = ex * f2.x; a[5] = ex * f2.y; a[6] = ex * f3.x; a[7] = ex * f3.y;
    }

    int i = beg;
    int   s0 = 0, s1 = 0;
    float al0 = 0.f, al1 = 0.f;
    if (i     < end) { s0 = csr[i];     al0 = as_[s0]; }
    if (i + 1 < end) { s1 = csr[i + 1]; al1 = as_[s1]; }
    for (; i + 2 <= end; i += 2) {
        int   s2 = 0, s3 = 0;
        float al2 = 0.f, al3 = 0.f;
        if (i + 2 < end) { s2 = csr[i + 2]; al2 = as_[s2]; }
        if (i + 3 < end) { s3 = csr[i + 3]; al3 = as_[s3]; }
        uint4 u0 = *(const uint4*)&h2h[(size_t)s0 * EMB + c0];
        uint4 u1 = *(const uint4*)&h2h[(size_t)s1 * EMB + c0];
        float e0 = safexp(lrelu(al0 + adv));
        float e1 = safexp(lrelu(al1 + adv));
        den += e0 + e1;
        float2 f0 = __half22float2(*(__half2*)&u0.x);
        float2 f1 = __half22float2(*(__half2*)&u0.y);
        float2 f2 = __half22float2(*(__half2*)&u0.z);
        float2 f3 = __half22float2(*(__half2*)&u0.w);
        float2 g0 = __half22float2(*(__half2*)&u1.x);
        float2 g1 = __half22float2(*(__half2*)&u1.y);
        float2 g2 = __half22float2(*(__half2*)&u1.z);
        float2 g3 = __half22float2(*(__half2*)&u1.w);
        a[0] += e0 * f0.x + e1 * g0.x; a[1] += e0 * f0.y + e1 * g0.y;
        a[2] += e0 * f1.x + e1 * g1.x; a[3] += e0 * f1.y + e1 * g1.y;
        a[4] += e0 * f2.x + e1 * g2.x; a[5] += e0 * f2.y + e1 * g2.y;
        a[6] += e0 * f3.x + e1 * g3.x; a[7] += e0 * f3.y + e1 * g3.y;
        s0 = s2; al0 = al2; s1 = s3; al1 = al3;
    }
    if (i < end) {
        uint4 u0 = *(const uint4*)&h2h[(size_t)s0 * EMB + c0];
        float e0 = safexp(lrelu(al0 + adv));
        den += e0;
        float2 f0 = __half22float2(*(__half2*)&u0.x);
        float2 f1 = __half22float2(*(__half2*)&u0.y);
        float2 f2 = __half22float2(*(__half2*)&u0.z);
        float2 f3 = __half22float2(*(__half2*)&u0.w);
        a[0] += e0 * f0.x; a[1] += e0 * f0.y; a[2] += e0 * f1.x; a[3] += e0 * f1.y;
        a[4] += e0 * f2.x; a[5] += e0 * f2.y; a[6] += e0 * f3.x; a[7] += e0 * f3.y;
    }

    const float inv = 1.f / den;
    float4 o0, o1;
    o0.x = a[0] * inv + b2[c0 + 0];
    o0.y = a[1] * inv + b2[c0 + 1];
    o0.z = a[2] * inv + b2[c0 + 2];
    o0.w = a[3] * inv + b2[c0 + 3];
    o1.x = a[4] * inv + b2[c0 + 4];
    o1.y = a[5] * inv + b2[c0 + 5];
    o1.z = a[6] * inv + b2[c0 + 6];
    o1.w = a[7] * inv + b2[c0 + 7];
    *(float4*)&out[(size_t)n * EMB + c0]     = o0;
    *(float4*)&out[(size_t)n * EMB + c0 + 4] = o1;
}

// ================= launch =================
extern "C" void kernel_launch(void* const* d_in, const int* in_sizes, int n_in,
                              void* d_out, int out_size) {
    const float* x      = (const float*)d_in[0];
    const int*   ei     = (const int*)d_in[1];     // int32 (JAX x64 disabled)
    const float* W1     = (const float*)d_in[2];
    const float* a_src1 = (const float*)d_in[3];
    const float* a_dst1 = (const float*)d_in[4];
    const float* b1     = (const float*)d_in[5];
    const float* W2     = (const float*)d_in[6];
    const float* a_src2 = (const float*)d_in[7];
    const float* a_dst2 = (const float*)d_in[8];
    const float* b2     = (const float*)d_in[9];
    float* out = (float*)d_out;

    const int N = in_sizes[0] / IND;
    const int E = in_sizes[1] / 2;

    __half *p_xh, *p_w1t, *p_w2t, *p_h1h, *p_h1eh, *p_h2h;
    float *p_alpha;
    int *p_cnt, *p_ptr, *p_cur, *p_csr;
    cudaGetSymbolAddress((void**)&p_xh,   g_xh);
    cudaGetSymbolAddress((void**)&p_w1t,  g_w1t);
    cudaGetSymbolAddress((void**)&p_w2t,  g_w2t);
    cudaGetSymbolAddress((void**)&p_h1h,  g_h1h);
    cudaGetSymbolAddress((void**)&p_h1eh, g_h1eh);
    cudaGetSymbolAddress((void**)&p_h2h,  g_h2h);
    cudaGetSymbolAddress((void**)&p_alpha,g_alpha);
    cudaGetSymbolAddress((void**)&p_cnt,  g_cnt);
    cudaGetSymbolAddress((void**)&p_ptr,  g_ptr);
    cudaGetSymbolAddress((void**)&p_cur,  g_cur);
    cudaGetSymbolAddress((void**)&p_csr,  g_csr);

    float* p_as1 = p_alpha;
    float* p_ad1 = p_alpha + NN * HEADS;
    float* p_as2 = p_alpha + 2 * NN * HEADS;
    float* p_ad2 = p_alpha + 2 * NN * HEADS + NN;

    static cudaStream_t side = nullptr;
    static cudaEvent_t evFork = nullptr, evJoin = nullptr;
    static bool inited = false;
    if (!inited) {
        cudaFuncSetAttribute(hgemm_kernel,
                             cudaFuncAttributeMaxDynamicSharedMemorySize, GEMM_SMEM);
        cudaStreamCreateWithFlags(&side, cudaStreamNonBlocking);
        cudaEventCreateWithFlags(&evFork, cudaEventDisableTiming);
        cudaEventCreateWithFlags(&evJoin, cudaEventDisableTiming);
        inited = true;
    }

    const int T = 256;

    // ---- fork side stream: zero + CSR build (hidden under prep+GEMM1) ----
    cudaEventRecord(evFork, 0);
    cudaStreamWaitEvent(side, evFork, 0);
    init_zero_kernel<<<(ALPHA_TOT + T - 1) / T, T, 0, side>>>(p_alpha, ALPHA_TOT, p_cnt, N);
    csr_count_kernel<<<(E + T - 1) / T, T, 0, side>>>(ei, E, p_cnt);
    csr_scan_kernel<<<1, 1024, 0, side>>>(p_cnt, p_ptr, p_cur, N);
    csr_scatter_kernel<<<(E + T - 1) / T, T, 0, side>>>(ei, E, p_cur, p_csr);
    cudaEventRecord(evJoin, side);

    // ---- main: fp16 prep ----
    f2h_kernel<<<(N * IND / 4 + T - 1) / T, T>>>(x, p_xh, N * IND / 4);
    wt_kernel<<<(IND * D1 + T - 1) / T, T>>>(W1, p_w1t, IND, D1);
    wt_kernel<<<(D1 * EMB + T - 1) / T, T>>>(W2, p_w2t, D1, EMB);

    // ---- GEMM1 + fused alphas1 ----
    {
        dim3 grid(D1 / 128, (N + 127) / 128);
        hgemm_kernel<<<grid, 256, GEMM_SMEM>>>(
            p_xh, p_w1t, p_h1h, N, D1, IND, p_as1, p_ad1, a_src1, a_dst1, HID);
    }

    // join: aggr1 needs the CSR
    cudaStreamWaitEvent(0, evJoin, 0);

    // ---- fused layer-1 aggregation (2 warps per head) ----
    aggr1_kernel<<<N, 512>>>(p_ptr, p_csr, p_as1, p_ad1, p_h1h, b1, p_h1eh);

    // ---- GEMM2 + fused alphas2 ----
    {
        dim3 grid(EMB / 128, (N + 127) / 128);
        hgemm_kernel<<<grid, 256, GEMM_SMEM>>>(
            p_h1eh, p_w2t, p_h2h, N, EMB, D1, p_as2, p_ad2, a_src2, a_dst2, EMB);
    }

    // ---- fused layer-2 aggregation -> d_out ----
    aggr2_kernel<<<(N * 32 + T - 1) / T, T>>>(p_ptr, p_csr, p_as2, p_ad2, p_h2h, b2, out, N);
}

// round 13
// speedup vs baseline: 1.1304x; 1.1304x over previous
#include <cuda_runtime.h>
#include <cuda_fp16.h>
#include <math.h>
#include <stdint.h>

// Problem constants (fixed by the dataset)
#define NN      10000        // nodes
#define EE      160000       // edges (before self loops)
#define IND     512
#define HID     128
#define HEADS   8
#define D1      (HEADS*HID)  // 1024
#define EMB     256

// ---------------- scratch (static __device__, no allocation) ----------------
__device__ __align__(16) __half g_xh  [NN * IND];
__device__ __align__(16) __half g_w1t [IND * D1];
__device__ __align__(16) __half g_w2t [D1 * EMB];
__device__ __align__(16) __half g_h1h [NN * D1];
__device__ __align__(16) __half g_h1eh[NN * D1];
__device__ __align__(16) __half g_h2h [NN * EMB];
#define ALPHA_TOT (2*NN*HEADS + 2*NN)
__device__ float g_alpha[ALPHA_TOT];  // [as1 | ad1 | as2 | ad2]
__device__ int   g_cnt[NN];
__device__ int   g_ptr[NN + 1];
__device__ int   g_cur[NN];
__device__ int   g_csr[EE];

// ---------------- helpers ----------------
__device__ __forceinline__ void mma_f16(float d[4],
        uint32_t a0, uint32_t a1, uint32_t a2, uint32_t a3,
        uint32_t b0, uint32_t b1) {
    asm volatile(
        "mma.sync.aligned.m16n8k16.row.col.f32.f16.f16.f32 "
        "{%0,%1,%2,%3}, {%4,%5,%6,%7}, {%8,%9}, {%0,%1,%2,%3};"
        : "+f"(d[0]), "+f"(d[1]), "+f"(d[2]), "+f"(d[3])
        : "r"(a0), "r"(a1), "r"(a2), "r"(a3), "r"(b0), "r"(b1));
}

__device__ __forceinline__ void ldmatrix_x4(uint32_t r[4], uint32_t addr) {
    asm volatile("ldmatrix.sync.aligned.m8n8.x4.shared.b16 {%0,%1,%2,%3}, [%4];"
                 : "=r"(r[0]), "=r"(r[1]), "=r"(r[2]), "=r"(r[3]) : "r"(addr));
}

__device__ __forceinline__ void ldmatrix_x2(uint32_t r[2], uint32_t addr) {
    asm volatile("ldmatrix.sync.aligned.m8n8.x2.shared.b16 {%0,%1}, [%2];"
                 : "=r"(r[0]), "=r"(r[1]) : "r"(addr));
}

__device__ __forceinline__ void cpAsync16(uint32_t dst_smem, const void* src, bool valid) {
    int sz = valid ? 16 : 0;
    asm volatile("cp.async.cg.shared.global [%0], [%1], 16, %2;"
                 :: "r"(dst_smem), "l"(src), "r"(sz));
}

__device__ __forceinline__ float lrelu(float v) { return v > 0.f ? v : 0.2f * v; }
__device__ __forceinline__ float safexp(float v) { return __expf(fminf(v, 80.f)); }

// ================= prep: fp32 -> fp16 convert / transpose =================
__global__ void f2h_kernel(const float* __restrict__ in, __half* __restrict__ out, int n4) {
    int i = blockIdx.x * blockDim.x + threadIdx.x;
    if (i >= n4) return;
    float4 v = ((const float4*)in)[i];
    __half2 h0 = __floats2half2_rn(v.x, v.y);
    __half2 h1 = __floats2half2_rn(v.z, v.w);
    ((uint2*)out)[i] = make_uint2(*(uint32_t*)&h0, *(uint32_t*)&h1);
}

__global__ void wt_kernel(const float* __restrict__ W, __half* __restrict__ Wt,
                          int K, int N) {
    int idx = blockIdx.x * blockDim.x + threadIdx.x;
    if (idx >= K * N) return;
    int k = idx / N, n = idx % N;
    Wt[(size_t)n * K + k] = __float2half(W[idx]);
}

// ================= init: zero alphas + cnt (side stream) =================
__global__ void init_zero_kernel(float* alpha, int na, int* cnt, int nc) {
    int i = blockIdx.x * blockDim.x + threadIdx.x;
    if (i < na) alpha[i] = 0.f;
    if (i < nc) cnt[i] = 0;
}

// ================= CSR build =================
__global__ void csr_count_kernel(const int* __restrict__ ei, int E, int* cnt) {
    int e = blockIdx.x * blockDim.x + threadIdx.x;
    if (e < E) atomicAdd(&cnt[ei[E + e]], 1);
}

__global__ void csr_scan_kernel(const int* __restrict__ cnt, int* __restrict__ ptr,
                                int* __restrict__ cur, int N) {
    __shared__ int sm[1024];
    __shared__ int carry_s;
    int tid = threadIdx.x;
    if (tid == 0) { carry_s = 0; ptr[0] = 0; }
    __syncthreads();
    for (int base = 0; base < N; base += 1024) {
        int i = base + tid;
        int v = (i < N) ? cnt[i] : 0;
        sm[tid] = v;
        __syncthreads();
        #pragma unroll
        for (int off = 1; off < 1024; off <<= 1) {
            int t = (tid >= off) ? sm[tid - off] : 0;
            __syncthreads();
            sm[tid] += t;
            __syncthreads();
        }
        int carry = carry_s;
        if (i < N) {
            ptr[i + 1] = carry + sm[tid];
            cur[i]     = carry + sm[tid] - v;
        }
        __syncthreads();
        if (tid == 1023) carry_s = carry + sm[1023];
        __syncthreads();
    }
}

__global__ void csr_scatter_kernel(const int* __restrict__ ei, int E,
                                   int* cur, int* __restrict__ csr) {
    int e = blockIdx.x * blockDim.x + threadIdx.x;
    if (e >= E) return;
    int src = ei[e], dst = ei[E + e];
    int pos = atomicAdd(&cur[dst], 1);
    csr[pos] = src;
}

// ================= fp16 HMMA GEMM (m16n8k16), ldmatrix fragments ============
#define KT    32
#define STRH  40
#define GEMM_SMEM ((2*128*STRH + 2*128*STRH) * 2)   // 40960 bytes

__global__ __launch_bounds__(256, 2) void hgemm_kernel(
        const __half* __restrict__ A, const __half* __restrict__ Bt,
        __half* __restrict__ Ch, int M, int N, int K,
        float* as_, float* ad_,
        const float* __restrict__ avs, const float* __restrict__ avd, int HC) {
    extern __shared__ __half smh[];
    uint32_t smbase = (uint32_t)__cvta_generic_to_shared(smh);
    uint32_t asb[2] = { smbase, smbase + 128 * STRH * 2 };
    uint32_t bsb[2] = { smbase + 2 * 128 * STRH * 2, smbase + 3 * 128 * STRH * 2 };

    const int tid   = threadIdx.x;
    const int lane  = tid & 31;
    const int w     = tid >> 5;
    const int warp_m = (w & 1) * 64;
    const int warp_n = (w >> 1) * 32;
    const int lq = lane >> 2;
    const int lr = lane & 3;

    const int row0 = blockIdx.y * 128;
    const int col0 = blockIdx.x * 128;
    const int T = K / KT;

    float acc[4][4][4];
    #pragma unroll
    for (int mf = 0; mf < 4; mf++)
        #pragma unroll
        for (int nf = 0; nf < 4; nf++)
            #pragma unroll
            for (int c = 0; c < 4; c++) acc[mf][nf][c] = 0.f;

    const int ldR = tid >> 2;
    const int ldC = (tid & 3) * 8;

    auto loadTile = [&](int t, int s) {
        const int k0 = t * KT;
        #pragma unroll
        for (int i = 0; i < 2; i++) {
            int m = ldR + 64 * i;
            int r = row0 + m;
            bool ok = (r < M);
            const __half* src = A + (size_t)(ok ? r : 0) * K + k0 + ldC;
            cpAsync16(asb[s] + (m * STRH + ldC) * 2, src, ok);
        }
        #pragma unroll
        for (int i = 0; i < 2; i++) {
            int n = ldR + 64 * i;
            const __half* src = Bt + (size_t)(col0 + n) * K + k0 + ldC;
            cpAsync16(bsb[s] + (n * STRH + ldC) * 2, src, true);
        }
        asm volatile("cp.async.commit_group;");
    };

    // ldmatrix lane->address maps (byte offsets within the tile)
    const int aRowL = lane & 15, aColL = (lane >> 4) * 8;
    const int bRowL = lane & 7,  bColL = ((lane >> 3) & 1) * 8;
    uint32_t aOff[4], bOff[4];
    #pragma unroll
    for (int mf = 0; mf < 4; mf++)
        aOff[mf] = ((warp_m + mf * 16 + aRowL) * STRH + aColL) * 2;
    #pragma unroll
    for (int nf = 0; nf < 4; nf++)
        bOff[nf] = ((warp_n + nf * 8 + bRowL) * STRH + bColL) * 2;

    loadTile(0, 0);

    for (int t = 0; t < T; t++) {
        const int s = t & 1;
        if (t + 1 < T) {
            loadTile(t + 1, 1 - s);
            asm volatile("cp.async.wait_group 1;");
        } else {
            asm volatile("cp.async.wait_group 0;");
        }
        __syncthreads();

        #pragma unroll
        for (int ks = 0; ks < 2; ks++) {
            const uint32_t kb = ks * 16 * 2;   // byte offset of k chunk
            uint32_t af[4][4], bf[4][2];
            #pragma unroll
            for (int mf = 0; mf < 4; mf++)
                ldmatrix_x4(af[mf], asb[s] + aOff[mf] + kb);
            #pragma unroll
            for (int nf = 0; nf < 4; nf++)
                ldmatrix_x2(bf[nf], bsb[s] + bOff[nf] + kb);
            #pragma unroll
            for (int mf = 0; mf < 4; mf++)
                #pragma unroll
                for (int nf = 0; nf < 4; nf++)
                    mma_f16(acc[mf][nf], af[mf][0], af[mf][1], af[mf][2], af[mf][3],
                            bf[nf][0], bf[nf][1]);
        }
        __syncthreads();
    }

    // store C as fp16
    #pragma unroll
    for (int mf = 0; mf < 4; mf++) {
        int r = row0 + warp_m + mf * 16 + lq;
        #pragma unroll
        for (int nf = 0; nf < 4; nf++) {
            int c = col0 + warp_n + nf * 8 + lr * 2;
            if (r < M)
                *(__half2*)&Ch[(size_t)r * N + c] =
                    __floats2half2_rn(acc[mf][nf][0], acc[mf][nf][1]);
            if (r + 8 < M)
                *(__half2*)&Ch[(size_t)(r + 8) * N + c] =
                    __floats2half2_rn(acc[mf][nf][2], acc[mf][nf][3]);
        }
    }

    // fused alpha epilogue
    {
        const int H    = N / HC;
        const int head = col0 / HC;
        float vs[4][2], vd[4][2];
        #pragma unroll
        for (int nf = 0; nf < 4; nf++) {
            int c = col0 + warp_n + nf * 8 + lr * 2;
            vs[nf][0] = avs[c];     vs[nf][1] = avs[c + 1];
            vd[nf][0] = avd[c];     vd[nf][1] = avd[c + 1];
        }
        #pragma unroll
        for (int mf = 0; mf < 4; mf++) {
            float s1a = 0.f, s2a = 0.f, s1b = 0.f, s2b = 0.f;
            #pragma unroll
            for (int nf = 0; nf < 4; nf++) {
                s1a += acc[mf][nf][0] * vs[nf][0] + acc[mf][nf][1] * vs[nf][1];
                s2a += acc[mf][nf][0] * vd[nf][0] + acc[mf][nf][1] * vd[nf][1];
                s1b += acc[mf][nf][2] * vs[nf][0] + acc[mf][nf][3] * vs[nf][1];
                s2b += acc[mf][nf][2] * vd[nf][0] + acc[mf][nf][3] * vd[nf][1];
            }
            #pragma unroll
            for (int off = 1; off < 4; off <<= 1) {
                s1a += __shfl_xor_sync(0xFFFFFFFFu, s1a, off);
                s2a += __shfl_xor_sync(0xFFFFFFFFu, s2a, off);
                s1b += __shfl_xor_sync(0xFFFFFFFFu, s1b, off);
                s2b += __shfl_xor_sync(0xFFFFFFFFu, s2b, off);
            }
            if (lr == 0) {
                int r = row0 + warp_m + mf * 16 + lq;
                if (r < M) {
                    atomicAdd(&as_[r * H + head], s1a);
                    atomicAdd(&ad_[r * H + head], s2a);
                }
                if (r + 8 < M) {
                    atomicAdd(&as_[(r + 8) * H + head], s1b);
                    atomicAdd(&ad_[(r + 8) * H + head], s2b);
                }
            }
        }
    }
}

// ================= layer-1 fused aggregation (R11 winner form) =============
__global__ __launch_bounds__(256) void aggr1_kernel(
        const int* __restrict__ ptr, const int* __restrict__ csr,
        const float* __restrict__ as_, const float* __restrict__ ad_,
        const __half* __restrict__ h1h, const float* __restrict__ b1,
        __half* __restrict__ h1eh) {
    const int n    = blockIdx.x;
    const int hh   = threadIdx.x >> 5;
    const int lane = threadIdx.x & 31;
    const int beg = ptr[n], end = ptr[n + 1];
    const float adv = ad_[n * HEADS + hh];
    const int ch = hh * HID + lane * 4;

    float4 acc;
    float den;
    {   // self loop
        float ex = safexp(lrelu(as_[n * HEADS + hh] + adv));
        den = ex;
        uint2 u = *(const uint2*)&h1h[(size_t)n * D1 + ch];
        float2 f0 = __half22float2(*(__half2*)&u.x);
        float2 f1 = __half22float2(*(__half2*)&u.y);
        acc.x = ex * f0.x; acc.y = ex * f0.y; acc.z = ex * f1.x; acc.w = ex * f1.y;
    }

    int i = beg;
    int   s0 = 0, s1 = 0;
    float a0 = 0.f, a1 = 0.f;
    if (i     < end) { s0 = csr[i];     a0 = as_[s0 * HEADS + hh]; }
    if (i + 1 < end) { s1 = csr[i + 1]; a1 = as_[s1 * HEADS + hh]; }
    for (; i + 2 <= end; i += 2) {
        int   s2 = 0, s3 = 0;
        float a2 = 0.f, a3 = 0.f;
        if (i + 2 < end) { s2 = csr[i + 2]; a2 = as_[s2 * HEADS + hh]; }
        if (i + 3 < end) { s3 = csr[i + 3]; a3 = as_[s3 * HEADS + hh]; }
        uint2 u0 = *(const uint2*)&h1h[(size_t)s0 * D1 + ch];
        uint2 u1 = *(const uint2*)&h1h[(size_t)s1 * D1 + ch];
        float e0 = safexp(lrelu(a0 + adv));
        float e1 = safexp(lrelu(a1 + adv));
        den += e0 + e1;
        float2 p0 = __half22float2(*(__half2*)&u0.x);
        float2 p1 = __half22float2(*(__half2*)&u0.y);
        float2 q0 = __half22float2(*(__half2*)&u1.x);
        float2 q1 = __half22float2(*(__half2*)&u1.y);
        acc.x += e0 * p0.x + e1 * q0.x;
        acc.y += e0 * p0.y + e1 * q0.y;
        acc.z += e0 * p1.x + e1 * q1.x;
        acc.w += e0 * p1.y + e1 * q1.y;
        s0 = s2; a0 = a2; s1 = s3; a1 = a3;
    }
    if (i < end) {
        uint2 u0 = *(const uint2*)&h1h[(size_t)s0 * D1 + ch];
        float e0 = safexp(lrelu(a0 + adv));
        den += e0;
        float2 p0 = __half22float2(*(__half2*)&u0.x);
        float2 p1 = __half22float2(*(__half2*)&u0.y);
        acc.x += e0 * p0.x; acc.y += e0 * p0.y;
        acc.z += e0 * p1.x; acc.w += e0 * p1.y;
    }

    const float inv = 1.f / den;
    float x0 = acc.x * inv + b1[ch + 0];
    float x1 = acc.y * inv + b1[ch + 1];
    float x2 = acc.z * inv + b1[ch + 2];
    float x3 = acc.w * inv + b1[ch + 3];
    x0 = x0 > 0.f ? x0 : expm1f(x0);
    x1 = x1 > 0.f ? x1 : expm1f(x1);
    x2 = x2 > 0.f ? x2 : expm1f(x2);
    x3 = x3 > 0.f ? x3 : expm1f(x3);
    __half2 ho0 = __floats2half2_rn(x0, x1);
    __half2 ho1 = __floats2half2_rn(x2, x3);
    *(uint2*)&h1eh[(size_t)n * D1 + ch] =
        make_uint2(*(uint32_t*)&ho0, *(uint32_t*)&ho1);
}

// ================= layer-2 fused aggregation =================
__global__ __launch_bounds__(256) void aggr2_kernel(
        const int* __restrict__ ptr, const int* __restrict__ csr,
        const float* __restrict__ as_, const float* __restrict__ ad_,
        const __half* __restrict__ h2h, const float* __restrict__ b2,
        float* __restrict__ out, int N) {
    const int n    = (blockIdx.x * blockDim.x + threadIdx.x) >> 5;
    const int lane = threadIdx.x & 31;
    if (n >= N) return;
    const int beg = ptr[n], end = ptr[n + 1];
    const float adv = ad_[n];
    const int c0 = lane * 8;

    float a[8];
    float den;
    {   // self loop
        float ex = safexp(lrelu(as_[n] + adv));
        den = ex;
        uint4 u = *(const uint4*)&h2h[(size_t)n * EMB + c0];
        float2 f0 = __half22float2(*(__half2*)&u.x);
        float2 f1 = __half22float2(*(__half2*)&u.y);
        float2 f2 = __half22float2(*(__half2*)&u.z);
        float2 f3 = __half22float2(*(__half2*)&u.w);
        a[0] = ex * f0.x; a[1] = ex * f0.y; a[2] = ex * f1.x; a[3] = ex * f1.y;
        a[4] = ex * f2.x; a[5] = ex * f2.y; a[6] = ex * f3.x; a[7] = ex * f3.y;
    }

    int i = beg;
    int   s0 = 0, s1 = 0;
    float al0 = 0.f, al1 = 0.f;
    if (i     < end) { s0 = csr[i];     al0 = as_[s0]; }
    if (i + 1 < end) { s1 = csr[i + 1]; al1 = as_[s1]; }
    for (; i + 2 <= end; i += 2) {
        int   s2 = 0, s3 = 0;
        float al2 = 0.f, al3 = 0.f;
        if (i + 2 < end) { s2 = csr[i + 2]; al2 = as_[s2]; }
        if (i + 3 < end) { s3 = csr[i + 3]; al3 = as_[s3]; }
        uint4 u0 = *(const uint4*)&h2h[(size_t)s0 * EMB + c0];
        uint4 u1 = *(const uint4*)&h2h[(size_t)s1 * EMB + c0];
        float e0 = safexp(lrelu(al0 + adv));
        float e1 = safexp(lrelu(al1 + adv));
        den += e0 + e1;
        float2 f0 = __half22float2(*(__half2*)&u0.x);
        float2 f1 = __half22float2(*(__half2*)&u0.y);
        float2 f2 = __half22float2(*(__half2*)&u0.z);
        float2 f3 = __half22float2(*(__half2*)&u0.w);
        float2 g0 = __half22float2(*(__half2*)&u1.x);
        float2 g1 = __half22float2(*(__half2*)&u1.y);
        float2 g2 = __half22float2(*(__half2*)&u1.z);
        float2 g3 = __half22float2(*(__half2*)&u1.w);
        a[0] += e0 * f0.x + e1 * g0.x; a[1] += e0 * f0.y + e1 * g0.y;
        a[2] += e0 * f1.x + e1 * g1.x; a[3] += e0 * f1.y + e1 * g1.y;
        a[4] += e0 * f2.x + e1 * g2.x; a[5] += e0 * f2.y + e1 * g2.y;
        a[6] += e0 * f3.x + e1 * g3.x; a[7] += e0 * f3.y + e1 * g3.y;
        s0 = s2; al0 = al2; s1 = s3; al1 = al3;
    }
    if (i < end) {
        uint4 u0 = *(const uint4*)&h2h[(size_t)s0 * EMB + c0];
        float e0 = safexp(lrelu(al0 + adv));
        den += e0;
        float2 f0 = __half22float2(*(__half2*)&u0.x);
        float2 f1 = __half22float2(*(__half2*)&u0.y);
        float2 f2 = __half22float2(*(__half2*)&u0.z);
        float2 f3 = __half22float2(*(__half2*)&u0.w);
        a[0] += e0 * f0.x; a[1] += e0 * f0.y; a[2] += e0 * f1.x; a[3] += e0 * f1.y;
        a[4] += e0 * f2.x; a[5] += e0 * f2.y; a[6] += e0 * f3.x; a[7] += e0 * f3.y;
    }

    const float inv = 1.f / den;
    float4 o0, o1;
    o0.x = a[0] * inv + b2[c0 + 0];
    o0.y = a[1] * inv + b2[c0 + 1];
    o0.z = a[2] * inv + b2[c0 + 2];
    o0.w = a[3] * inv + b2[c0 + 3];
    o1.x = a[4] * inv + b2[c0 + 4];
    o1.y = a[5] * inv + b2[c0 + 5];
    o1.z = a[6] * inv + b2[c0 + 6];
    o1.w = a[7] * inv + b2[c0 + 7];
    *(float4*)&out[(size_t)n * EMB + c0]     = o0;
    *(float4*)&out[(size_t)n * EMB + c0 + 4] = o1;
}

// ================= launch =================
extern "C" void kernel_launch(void* const* d_in, const int* in_sizes, int n_in,
                              void* d_out, int out_size) {
    const float* x      = (const float*)d_in[0];
    const int*   ei     = (const int*)d_in[1];     // int32 (JAX x64 disabled)
    const float* W1     = (const float*)d_in[2];
    const float* a_src1 = (const float*)d_in[3];
    const float* a_dst1 = (const float*)d_in[4];
    const float* b1     = (const float*)d_in[5];
    const float* W2     = (const float*)d_in[6];
    const float* a_src2 = (const float*)d_in[7];
    const float* a_dst2 = (const float*)d_in[8];
    const float* b2     = (const float*)d_in[9];
    float* out = (float*)d_out;

    const int N = in_sizes[0] / IND;
    const int E = in_sizes[1] / 2;

    __half *p_xh, *p_w1t, *p_w2t, *p_h1h, *p_h1eh, *p_h2h;
    float *p_alpha;
    int *p_cnt, *p_ptr, *p_cur, *p_csr;
    cudaGetSymbolAddress((void**)&p_xh,   g_xh);
    cudaGetSymbolAddress((void**)&p_w1t,  g_w1t);
    cudaGetSymbolAddress((void**)&p_w2t,  g_w2t);
    cudaGetSymbolAddress((void**)&p_h1h,  g_h1h);
    cudaGetSymbolAddress((void**)&p_h1eh, g_h1eh);
    cudaGetSymbolAddress((void**)&p_h2h,  g_h2h);
    cudaGetSymbolAddress((void**)&p_alpha,g_alpha);
    cudaGetSymbolAddress((void**)&p_cnt,  g_cnt);
    cudaGetSymbolAddress((void**)&p_ptr,  g_ptr);
    cudaGetSymbolAddress((void**)&p_cur,  g_cur);
    cudaGetSymbolAddress((void**)&p_csr,  g_csr);

    float* p_as1 = p_alpha;
    float* p_ad1 = p_alpha + NN * HEADS;
    float* p_as2 = p_alpha + 2 * NN * HEADS;
    float* p_ad2 = p_alpha + 2 * NN * HEADS + NN;

    static cudaStream_t side = nullptr;
    static cudaEvent_t evFork = nullptr, evJoin = nullptr;
    static bool inited = false;
    if (!inited) {
        cudaFuncSetAttribute(hgemm_kernel,
                             cudaFuncAttributeMaxDynamicSharedMemorySize, GEMM_SMEM);
        cudaStreamCreateWithFlags(&side, cudaStreamNonBlocking);
        cudaEventCreateWithFlags(&evFork, cudaEventDisableTiming);
        cudaEventCreateWithFlags(&evJoin, cudaEventDisableTiming);
        inited = true;
    }

    const int T = 256;

    // ---- fork side stream: zero + CSR build + W2 transpose (hidden) ----
    cudaEventRecord(evFork, 0);
    cudaStreamWaitEvent(side, evFork, 0);
    init_zero_kernel<<<(ALPHA_TOT + T - 1) / T, T, 0, side>>>(p_alpha, ALPHA_TOT, p_cnt, N);
    csr_count_kernel<<<(E + T - 1) / T, T, 0, side>>>(ei, E, p_cnt);
    csr_scan_kernel<<<1, 1024, 0, side>>>(p_cnt, p_ptr, p_cur, N);
    csr_scatter_kernel<<<(E + T - 1) / T, T, 0, side>>>(ei, E, p_cur, p_csr);
    wt_kernel<<<(D1 * EMB + T - 1) / T, T, 0, side>>>(W2, p_w2t, D1, EMB);
    cudaEventRecord(evJoin, side);

    // ---- main: fp16 prep needed by GEMM1 only ----
    f2h_kernel<<<(N * IND / 4 + T - 1) / T, T>>>(x, p_xh, N * IND / 4);
    wt_kernel<<<(IND * D1 + T - 1) / T, T>>>(W1, p_w1t, IND, D1);

    // ---- GEMM1 + fused alphas1 ----
    {
        dim3 grid(D1 / 128, (N + 127) / 128);
        hgemm_kernel<<<grid, 256, GEMM_SMEM>>>(
            p_xh, p_w1t, p_h1h, N, D1, IND, p_as1, p_ad1, a_src1, a_dst1, HID);
    }

    // join: aggr1 needs the CSR (and GEMM2 the W2 transpose)
    cudaStreamWaitEvent(0, evJoin, 0);

    // ---- fused layer-1 aggregation ----
    aggr1_kernel<<<N, 256>>>(p_ptr, p_csr, p_as1, p_ad1, p_h1h, b1, p_h1eh);

    // ---- GEMM2 + fused alphas2 ----
    {
        dim3 grid(EMB / 128, (N + 127) / 128);
        hgemm_kernel<<<grid, 256, GEMM_SMEM>>>(
            p_h1eh, p_w2t, p_h2h, N, EMB, D1, p_as2, p_ad2, a_src2, a_dst2, EMB);
    }

    // ---- fused layer-2 aggregation -> d_out ----
    aggr2_kernel<<<(N * 32 + T - 1) / T, T>>>(p_ptr, p_csr, p_as2, p_ad2, p_h2h, b2, out, N);
}

// round 14
// speedup vs baseline: 1.1328x; 1.0021x over previous
#include <cuda_runtime.h>
#include <cuda_fp16.h>
#include <math.h>
#include <stdint.h>

// Problem constants (fixed by the dataset)
#define NN      10000        // nodes
#define EE      160000       // edges (before self loops)
#define IND     512
#define HID     128
#define HEADS   8
#define D1      (HEADS*HID)  // 1024
#define EMB     256

// ---------------- scratch (static __device__, no allocation) ----------------
__device__ __align__(16) __half g_xh  [NN * IND];
__device__ __align__(16) __half g_w1t [IND * D1];
__device__ __align__(16) __half g_w2t [D1 * EMB];
__device__ __align__(16) __half g_h1h [NN * D1];
__device__ __align__(16) __half g_h1eh[NN * D1];
__device__ __align__(16) __half g_h2h [NN * EMB];
#define ALPHA_TOT (2*NN*HEADS + 2*NN)
__device__ float g_alpha[ALPHA_TOT];  // [as1 | ad1 | as2 | ad2]
__device__ int   g_cnt[NN];
__device__ int   g_ptr[NN + 1];
__device__ int   g_cur[NN];
__device__ int   g_csr[EE];

// ---------------- helpers ----------------
__device__ __forceinline__ void mma_f16(float d[4],
        uint32_t a0, uint32_t a1, uint32_t a2, uint32_t a3,
        uint32_t b0, uint32_t b1) {
    asm volatile(
        "mma.sync.aligned.m16n8k16.row.col.f32.f16.f16.f32 "
        "{%0,%1,%2,%3}, {%4,%5,%6,%7}, {%8,%9}, {%0,%1,%2,%3};"
        : "+f"(d[0]), "+f"(d[1]), "+f"(d[2]), "+f"(d[3])
        : "r"(a0), "r"(a1), "r"(a2), "r"(a3), "r"(b0), "r"(b1));
}

__device__ __forceinline__ void ldmatrix_x4(uint32_t r[4], uint32_t addr) {
    asm volatile("ldmatrix.sync.aligned.m8n8.x4.shared.b16 {%0,%1,%2,%3}, [%4];"
                 : "=r"(r[0]), "=r"(r[1]), "=r"(r[2]), "=r"(r[3]) : "r"(addr));
}

__device__ __forceinline__ void ldmatrix_x2(uint32_t r[2], uint32_t addr) {
    asm volatile("ldmatrix.sync.aligned.m8n8.x2.shared.b16 {%0,%1}, [%2];"
                 : "=r"(r[0]), "=r"(r[1]) : "r"(addr));
}

__device__ __forceinline__ void cpAsync16(uint32_t dst_smem, const void* src, bool valid) {
    int sz = valid ? 16 : 0;
    asm volatile("cp.async.cg.shared.global [%0], [%1], 16, %2;"
                 :: "r"(dst_smem), "l"(src), "r"(sz));
}

__device__ __forceinline__ float lrelu(float v) { return v > 0.f ? v : 0.2f * v; }
__device__ __forceinline__ float safexp(float v) { return __expf(fminf(v, 80.f)); }

// ================= prep: f2h(x) + W1 transpose + zero alpha + zero cnt =====
// One kernel, all independent element-wise work. Grid covers the largest job.
__global__ void prep_kernel(const float* __restrict__ x, __half* __restrict__ xh,
                            const float* __restrict__ W1, __half* __restrict__ w1t,
                            float* __restrict__ alpha, int* __restrict__ cnt,
                            int nx4) {
    int i = blockIdx.x * blockDim.x + threadIdx.x;
    if (i < nx4) {
        float4 v = ((const float4*)x)[i];
        __half2 h0 = __floats2half2_rn(v.x, v.y);
        __half2 h1 = __floats2half2_rn(v.z, v.w);
        ((uint2*)xh)[i] = make_uint2(*(uint32_t*)&h0, *(uint32_t*)&h1);
    }
    if (i < IND * D1) {
        int k = i / D1, n = i % D1;
        w1t[(size_t)n * IND + k] = __float2half(W1[i]);
    }
    if (i < ALPHA_TOT) alpha[i] = 0.f;
    if (i < NN)        cnt[i] = 0;
}

// ================= CSR count =================
__global__ void csr_count_kernel(const int* __restrict__ ei, int E, int* cnt) {
    int e = blockIdx.x * blockDim.x + threadIdx.x;
    if (e < E) atomicAdd(&cnt[ei[E + e]], 1);
}

// ================= scan (block 0) + W2 transpose (blocks 1..) ==============
__global__ void scan_wt2_kernel(const int* __restrict__ cnt, int* __restrict__ ptr,
                                int* __restrict__ cur, int N,
                                const float* __restrict__ W2, __half* __restrict__ w2t) {
    if (blockIdx.x == 0) {
        __shared__ int sm[1024];
        __shared__ int carry_s;
        int tid = threadIdx.x;
        if (tid == 0) { carry_s = 0; ptr[0] = 0; }
        __syncthreads();
        for (int base = 0; base < N; base += 1024) {
            int i = base + tid;
            int v = (i < N) ? cnt[i] : 0;
            sm[tid] = v;
            __syncthreads();
            #pragma unroll
            for (int off = 1; off < 1024; off <<= 1) {
                int t = (tid >= off) ? sm[tid - off] : 0;
                __syncthreads();
                sm[tid] += t;
                __syncthreads();
            }
            int carry = carry_s;
            if (i < N) {
                ptr[i + 1] = carry + sm[tid];
                cur[i]     = carry + sm[tid] - v;
            }
            __syncthreads();
            if (tid == 1023) carry_s = carry + sm[1023];
            __syncthreads();
        }
    } else {
        // W2 transpose: D1*EMB elements across blocks 1..gridDim-1
        int idx = (blockIdx.x - 1) * blockDim.x + threadIdx.x;
        int stride = (gridDim.x - 1) * blockDim.x;
        for (; idx < D1 * EMB; idx += stride) {
            int k = idx / EMB, n = idx % EMB;
            w2t[(size_t)n * D1 + k] = __float2half(W2[idx]);
        }
    }
}

__global__ void csr_scatter_kernel(const int* __restrict__ ei, int E,
                                   int* cur, int* __restrict__ csr) {
    int e = blockIdx.x * blockDim.x + threadIdx.x;
    if (e >= E) return;
    int src = ei[e], dst = ei[E + e];
    int pos = atomicAdd(&cur[dst], 1);
    csr[pos] = src;
}

// ================= fp16 HMMA GEMM (m16n8k16), ldmatrix fragments ============
#define KT    32
#define STRH  40
#define GEMM_SMEM ((2*128*STRH + 2*128*STRH) * 2)   // 40960 bytes

__global__ __launch_bounds__(256, 2) void hgemm_kernel(
        const __half* __restrict__ A, const __half* __restrict__ Bt,
        __half* __restrict__ Ch, int M, int N, int K,
        float* as_, float* ad_,
        const float* __restrict__ avs, const float* __restrict__ avd, int HC) {
    extern __shared__ __half smh[];
    uint32_t smbase = (uint32_t)__cvta_generic_to_shared(smh);
    uint32_t asb[2] = { smbase, smbase + 128 * STRH * 2 };
    uint32_t bsb[2] = { smbase + 2 * 128 * STRH * 2, smbase + 3 * 128 * STRH * 2 };

    const int tid   = threadIdx.x;
    const int lane  = tid & 31;
    const int w     = tid >> 5;
    const int warp_m = (w & 1) * 64;
    const int warp_n = (w >> 1) * 32;
    const int lq = lane >> 2;
    const int lr = lane & 3;

    const int row0 = blockIdx.y * 128;
    const int col0 = blockIdx.x * 128;
    const int T = K / KT;

    float acc[4][4][4];
    #pragma unroll
    for (int mf = 0; mf < 4; mf++)
        #pragma unroll
        for (int nf = 0; nf < 4; nf++)
            #pragma unroll
            for (int c = 0; c < 4; c++) acc[mf][nf][c] = 0.f;

    const int ldR = tid >> 2;
    const int ldC = (tid & 3) * 8;

    auto loadTile = [&](int t, int s) {
        const int k0 = t * KT;
        #pragma unroll
        for (int i = 0; i < 2; i++) {
            int m = ldR + 64 * i;
            int r = row0 + m;
            bool ok = (r < M);
            const __half* src = A + (size_t)(ok ? r : 0) * K + k0 + ldC;
            cpAsync16(asb[s] + (m * STRH + ldC) * 2, src, ok);
        }
        #pragma unroll
        for (int i = 0; i < 2; i++) {
            int n = ldR + 64 * i;
            const __half* src = Bt + (size_t)(col0 + n) * K + k0 + ldC;
            cpAsync16(bsb[s] + (n * STRH + ldC) * 2, src, true);
        }
        asm volatile("cp.async.commit_group;");
    };

    const int aRowL = lane & 15, aColL = (lane >> 4) * 8;
    const int bRowL = lane & 7,  bColL = ((lane >> 3) & 1) * 8;
    uint32_t aOff[4], bOff[4];
    #pragma unroll
    for (int mf = 0; mf < 4; mf++)
        aOff[mf] = ((warp_m + mf * 16 + aRowL) * STRH + aColL) * 2;
    #pragma unroll
    for (int nf = 0; nf < 4; nf++)
        bOff[nf] = ((warp_n + nf * 8 + bRowL) * STRH + bColL) * 2;

    loadTile(0, 0);

    for (int t = 0; t < T; t++) {
        const int s = t & 1;
        if (t + 1 < T) {
            loadTile(t + 1, 1 - s);
            asm volatile("cp.async.wait_group 1;");
        } else {
            asm volatile("cp.async.wait_group 0;");
        }
        __syncthreads();

        #pragma unroll
        for (int ks = 0; ks < 2; ks++) {
            const uint32_t kb = ks * 16 * 2;
            uint32_t af[4][4], bf[4][2];
            #pragma unroll
            for (int mf = 0; mf < 4; mf++)
                ldmatrix_x4(af[mf], asb[s] + aOff[mf] + kb);
            #pragma unroll
            for (int nf = 0; nf < 4; nf++)
                ldmatrix_x2(bf[nf], bsb[s] + bOff[nf] + kb);
            #pragma unroll
            for (int mf = 0; mf < 4; mf++)
                #pragma unroll
                for (int nf = 0; nf < 4; nf++)
                    mma_f16(acc[mf][nf], af[mf][0], af[mf][1], af[mf][2], af[mf][3],
                            bf[nf][0], bf[nf][1]);
        }
        __syncthreads();
    }

    #pragma unroll
    for (int mf = 0; mf < 4; mf++) {
        int r = row0 + warp_m + mf * 16 + lq;
        #pragma unroll
        for (int nf = 0; nf < 4; nf++) {
            int c = col0 + warp_n + nf * 8 + lr * 2;
            if (r < M)
                *(__half2*)&Ch[(size_t)r * N + c] =
                    __floats2half2_rn(acc[mf][nf][0], acc[mf][nf][1]);
            if (r + 8 < M)
                *(__half2*)&Ch[(size_t)(r + 8) * N + c] =
                    __floats2half2_rn(acc[mf][nf][2], acc[mf][nf][3]);
        }
    }

    // fused alpha epilogue
    {
        const int H    = N / HC;
        const int head = col0 / HC;
        float vs[4][2], vd[4][2];
        #pragma unroll
        for (int nf = 0; nf < 4; nf++) {
            int c = col0 + warp_n + nf * 8 + lr * 2;
            vs[nf][0] = avs[c];     vs[nf][1] = avs[c + 1];
            vd[nf][0] = avd[c];     vd[nf][1] = avd[c + 1];
        }
        #pragma unroll
        for (int mf = 0; mf < 4; mf++) {
            float s1a = 0.f, s2a = 0.f, s1b = 0.f, s2b = 0.f;
            #pragma unroll
            for (int nf = 0; nf < 4; nf++) {
                s1a += acc[mf][nf][0] * vs[nf][0] + acc[mf][nf][1] * vs[nf][1];
                s2a += acc[mf][nf][0] * vd[nf][0] + acc[mf][nf][1] * vd[nf][1];
                s1b += acc[mf][nf][2] * vs[nf][0] + acc[mf][nf][3] * vs[nf][1];
                s2b += acc[mf][nf][2] * vd[nf][0] + acc[mf][nf][3] * vd[nf][1];
            }
            #pragma unroll
            for (int off = 1; off < 4; off <<= 1) {
                s1a += __shfl_xor_sync(0xFFFFFFFFu, s1a, off);
                s2a += __shfl_xor_sync(0xFFFFFFFFu, s2a, off);
                s1b += __shfl_xor_sync(0xFFFFFFFFu, s1b, off);
                s2b += __shfl_xor_sync(0xFFFFFFFFu, s2b, off);
            }
            if (lr == 0) {
                int r = row0 + warp_m + mf * 16 + lq;
                if (r < M) {
                    atomicAdd(&as_[r * H + head], s1a);
                    atomicAdd(&ad_[r * H + head], s2a);
                }
                if (r + 8 < M) {
                    atomicAdd(&as_[(r + 8) * H + head], s1b);
                    atomicAdd(&ad_[(r + 8) * H + head], s2b);
                }
            }
        }
    }
}

// ================= layer-1 fused aggregation =================
__global__ __launch_bounds__(256) void aggr1_kernel(
        const int* __restrict__ ptr, const int* __restrict__ csr,
        const float* __restrict__ as_, const float* __restrict__ ad_,
        const __half* __restrict__ h1h, const float* __restrict__ b1,
        __half* __restrict__ h1eh) {
    const int n    = blockIdx.x;
    const int hh   = threadIdx.x >> 5;
    const int lane = threadIdx.x & 31;
    const int beg = ptr[n], end = ptr[n + 1];
    const float adv = ad_[n * HEADS + hh];
    const int ch = hh * HID + lane * 4;

    float4 acc;
    float den;
    {   // self loop
        float ex = safexp(lrelu(as_[n * HEADS + hh] + adv));
        den = ex;
        uint2 u = *(const uint2*)&h1h[(size_t)n * D1 + ch];
        float2 f0 = __half22float2(*(__half2*)&u.x);
        float2 f1 = __half22float2(*(__half2*)&u.y);
        acc.x = ex * f0.x; acc.y = ex * f0.y; acc.z = ex * f1.x; acc.w = ex * f1.y;
    }

    int i = beg;
    int   s0 = 0, s1 = 0;
    float a0 = 0.f, a1 = 0.f;
    if (i     < end) { s0 = csr[i];     a0 = as_[s0 * HEADS + hh]; }
    if (i + 1 < end) { s1 = csr[i + 1]; a1 = as_[s1 * HEADS + hh]; }
    for (; i + 2 <= end; i += 2) {
        int   s2 = 0, s3 = 0;
        float a2 = 0.f, a3 = 0.f;
        if (i + 2 < end) { s2 = csr[i + 2]; a2 = as_[s2 * HEADS + hh]; }
        if (i + 3 < end) { s3 = csr[i + 3]; a3 = as_[s3 * HEADS + hh]; }
        uint2 u0 = *(const uint2*)&h1h[(size_t)s0 * D1 + ch];
        uint2 u1 = *(const uint2*)&h1h[(size_t)s1 * D1 + ch];
        float e0 = safexp(lrelu(a0 + adv));
        float e1 = safexp(lrelu(a1 + adv));
        den += e0 + e1;
        float2 p0 = __half22float2(*(__half2*)&u0.x);
        float2 p1 = __half22float2(*(__half2*)&u0.y);
        float2 q0 = __half22float2(*(__half2*)&u1.x);
        float2 q1 = __half22float2(*(__half2*)&u1.y);
        acc.x += e0 * p0.x + e1 * q0.x;
        acc.y += e0 * p0.y + e1 * q0.y;
        acc.z += e0 * p1.x + e1 * q1.x;
        acc.w += e0 * p1.y + e1 * q1.y;
        s0 = s2; a0 = a2; s1 = s3; a1 = a3;
    }
    if (i < end) {
        uint2 u0 = *(const uint2*)&h1h[(size_t)s0 * D1 + ch];
        float e0 = safexp(lrelu(a0 + adv));
        den += e0;
        float2 p0 = __half22float2(*(__half2*)&u0.x);
        float2 p1 = __half22float2(*(__half2*)&u0.y);
        acc.x += e0 * p0.x; acc.y += e0 * p0.y;
        acc.z += e0 * p1.x; acc.w += e0 * p1.y;
    }

    const float inv = 1.f / den;
    float x0 = acc.x * inv + b1[ch + 0];
    float x1 = acc.y * inv + b1[ch + 1];
    float x2 = acc.z * inv + b1[ch + 2];
    float x3 = acc.w * inv + b1[ch + 3];
    x0 = x0 > 0.f ? x0 : expm1f(x0);
    x1 = x1 > 0.f ? x1 : expm1f(x1);
    x2 = x2 > 0.f ? x2 : expm1f(x2);
    x3 = x3 > 0.f ? x3 : expm1f(x3);
    __half2 ho0 = __floats2half2_rn(x0, x1);
    __half2 ho1 = __floats2half2_rn(x2, x3);
    *(uint2*)&h1eh[(size_t)n * D1 + ch] =
        make_uint2(*(uint32_t*)&ho0, *(uint32_t*)&ho1);
}

// ================= layer-2 fused aggregation =================
__global__ __launch_bounds__(256) void aggr2_kernel(
        const int* __restrict__ ptr, const int* __restrict__ csr,
        const float* __restrict__ as_, const float* __restrict__ ad_,
        const __half* __restrict__ h2h, const float* __restrict__ b2,
        float* __restrict__ out, int N) {
    const int n    = (blockIdx.x * blockDim.x + threadIdx.x) >> 5;
    const int lane = threadIdx.x & 31;
    if (n >= N) return;
    const int beg = ptr[n], end = ptr[n + 1];
    const float adv = ad_[n];
    const int c0 = lane * 8;

    float a[8];
    float den;
    {   // self loop
        float ex = safexp(lrelu(as_[n] + adv));
        den = ex;
        uint4 u = *(const uint4*)&h2h[(size_t)n * EMB + c0];
        float2 f0 = __half22float2(*(__half2*)&u.x);
        float2 f1 = __half22float2(*(__half2*)&u.y);
        float2 f2 = __half22float2(*(__half2*)&u.z);
        float2 f3 = __half22float2(*(__half2*)&u.w);
        a[0] = ex * f0.x; a[1] = ex * f0.y; a[2] = ex * f1.x; a[3] = ex * f1.y;
        a[4] = ex * f2.x; a[5] = ex * f2.y; a[6] = ex * f3.x; a[7] = ex * f3.y;
    }

    int i = beg;
    int   s0 = 0, s1 = 0;
    float al0 = 0.f, al1 = 0.f;
    if (i     < end) { s0 = csr[i];     al0 = as_[s0]; }
    if (i + 1 < end) { s1 = csr[i + 1]; al1 = as_[s1]; }
    for (; i + 2 <= end; i += 2) {
        int   s2 = 0, s3 = 0;
        float al2 = 0.f, al3 = 0.f;
        if (i + 2 < end) { s2 = csr[i + 2]; al2 = as_[s2]; }
        if (i + 3 < end) { s3 = csr[i + 3]; al3 = as_[s3]; }
        uint4 u0 = *(const uint4*)&h2h[(size_t)s0 * EMB + c0];
        uint4 u1 = *(const uint4*)&h2h[(size_t)s1 * EMB + c0];
        float e0 = safexp(lrelu(al0 + adv));
        float e1 = safexp(lrelu(al1 + adv));
        den += e0 + e1;
        float2 f0 = __half22float2(*(__half2*)&u0.x);
        float2 f1 = __half22float2(*(__half2*)&u0.y);
        float2 f2 = __half22float2(*(__half2*)&u0.z);
        float2 f3 = __half22float2(*(__half2*)&u0.w);
        float2 g0 = __half22float2(*(__half2*)&u1.x);
        float2 g1 = __half22float2(*(__half2*)&u1.y);
        float2 g2 = __half22float2(*(__half2*)&u1.z);
        float2 g3 = __half22float2(*(__half2*)&u1.w);
        a[0] += e0 * f0.x + e1 * g0.x; a[1] += e0 * f0.y + e1 * g0.y;
        a[2] += e0 * f1.x + e1 * g1.x; a[3] += e0 * f1.y + e1 * g1.y;
        a[4] += e0 * f2.x + e1 * g2.x; a[5] += e0 * f2.y + e1 * g2.y;
        a[6] += e0 * f3.x + e1 * g3.x; a[7] += e0 * f3.y + e1 * g3.y;
        s0 = s2; al0 = al2; s1 = s3; al1 = al3;
    }
    if (i < end) {
        uint4 u0 = *(const uint4*)&h2h[(size_t)s0 * EMB + c0];
        float e0 = safexp(lrelu(al0 + adv));
        den += e0;
        float2 f0 = __half22float2(*(__half2*)&u0.x);
        float2 f1 = __half22float2(*(__half2*)&u0.y);
        float2 f2 = __half22float2(*(__half2*)&u0.z);
        float2 f3 = __half22float2(*(__half2*)&u0.w);
        a[0] += e0 * f0.x; a[1] += e0 * f0.y; a[2] += e0 * f1.x; a[3] += e0 * f1.y;
        a[4] += e0 * f2.x; a[5] += e0 * f2.y; a[6] += e0 * f3.x; a[7] += e0 * f3.y;
    }

    const float inv = 1.f / den;
    float4 o0, o1;
    o0.x = a[0] * inv + b2[c0 + 0];
    o0.y = a[1] * inv + b2[c0 + 1];
    o0.z = a[2] * inv + b2[c0 + 2];
    o0.w = a[3] * inv + b2[c0 + 3];
    o1.x = a[4] * inv + b2[c0 + 4];
    o1.y = a[5] * inv + b2[c0 + 5];
    o1.z = a[6] * inv + b2[c0 + 6];
    o1.w = a[7] * inv + b2[c0 + 7];
    *(float4*)&out[(size_t)n * EMB + c0]     = o0;
    *(float4*)&out[(size_t)n * EMB + c0 + 4] = o1;
}

// ================= launch =================
extern "C" void kernel_launch(void* const* d_in, const int* in_sizes, int n_in,
                              void* d_out, int out_size) {
    const float* x      = (const float*)d_in[0];
    const int*   ei     = (const int*)d_in[1];     // int32 (JAX x64 disabled)
    const float* W1     = (const float*)d_in[2];
    const float* a_src1 = (const float*)d_in[3];
    const float* a_dst1 = (const float*)d_in[4];
    const float* b1     = (const float*)d_in[5];
    const float* W2     = (const float*)d_in[6];
    const float* a_src2 = (const float*)d_in[7];
    const float* a_dst2 = (const float*)d_in[8];
    const float* b2     = (const float*)d_in[9];
    float* out = (float*)d_out;

    const int N = in_sizes[0] / IND;
    const int E = in_sizes[1] / 2;

    __half *p_xh, *p_w1t, *p_w2t, *p_h1h, *p_h1eh, *p_h2h;
    float *p_alpha;
    int *p_cnt, *p_ptr, *p_cur, *p_csr;
    cudaGetSymbolAddress((void**)&p_xh,   g_xh);
    cudaGetSymbolAddress((void**)&p_w1t,  g_w1t);
    cudaGetSymbolAddress((void**)&p_w2t,  g_w2t);
    cudaGetSymbolAddress((void**)&p_h1h,  g_h1h);
    cudaGetSymbolAddress((void**)&p_h1eh, g_h1eh);
    cudaGetSymbolAddress((void**)&p_h2h,  g_h2h);
    cudaGetSymbolAddress((void**)&p_alpha,g_alpha);
    cudaGetSymbolAddress((void**)&p_cnt,  g_cnt);
    cudaGetSymbolAddress((void**)&p_ptr,  g_ptr);
    cudaGetSymbolAddress((void**)&p_cur,  g_cur);
    cudaGetSymbolAddress((void**)&p_csr,  g_csr);

    float* p_as1 = p_alpha;
    float* p_ad1 = p_alpha + NN * HEADS;
    float* p_as2 = p_alpha + 2 * NN * HEADS;
    float* p_ad2 = p_alpha + 2 * NN * HEADS + NN;

    static cudaStream_t side = nullptr;
    static cudaEvent_t evFork = nullptr, evJoin = nullptr;
    static bool inited = false;
    if (!inited) {
        cudaFuncSetAttribute(hgemm_kernel,
                             cudaFuncAttributeMaxDynamicSharedMemorySize, GEMM_SMEM);
        cudaStreamCreateWithFlags(&side, cudaStreamNonBlocking);
        cudaEventCreateWithFlags(&evFork, cudaEventDisableTiming);
        cudaEventCreateWithFlags(&evJoin, cudaEventDisableTiming);
        inited = true;
    }

    const int T = 256;

    // ---- 1. prep (main): f2h + W1^T + zero alpha + zero cnt ----
    {
        int nx4 = N * IND / 4;   // largest job: 1.28M
        prep_kernel<<<(nx4 + T - 1) / T, T>>>(x, p_xh, W1, p_w1t, p_alpha, p_cnt, nx4);
    }

    // ---- fork side stream AFTER prep (cnt now zeroed) ----
    cudaEventRecord(evFork, 0);
    cudaStreamWaitEvent(side, evFork, 0);
    csr_count_kernel<<<(E + T - 1) / T, T, 0, side>>>(ei, E, p_cnt);
    scan_wt2_kernel<<<257, 1024, 0, side>>>(p_cnt, p_ptr, p_cur, N, W2, p_w2t);
    csr_scatter_kernel<<<(E + T - 1) / T, T, 0, side>>>(ei, E, p_cur, p_csr);
    cudaEventRecord(evJoin, side);

    // ---- 2. GEMM1 + fused alphas1 (main, overlaps CSR build) ----
    {
        dim3 grid(D1 / 128, (N + 127) / 128);
        hgemm_kernel<<<grid, 256, GEMM_SMEM>>>(
            p_xh, p_w1t, p_h1h, N, D1, IND, p_as1, p_ad1, a_src1, a_dst1, HID);
    }

    // join: aggr1 needs the CSR; GEMM2 needs w2t
    cudaStreamWaitEvent(0, evJoin, 0);

    // ---- 3. fused layer-1 aggregation ----
    aggr1_kernel<<<N, 256>>>(p_ptr, p_csr, p_as1, p_ad1, p_h1h, b1, p_h1eh);

    // ---- 4. GEMM2 + fused alphas2 ----
    {
        dim3 grid(EMB / 128, (N + 127) / 128);
        hgemm_kernel<<<grid, 256, GEMM_SMEM>>>(
            p_h1eh, p_w2t, p_h2h, N, EMB, D1, p_as2, p_ad2, a_src2, a_dst2, EMB);
    }

    // ---- 5. fused layer-2 aggregation -> d_out ----
    aggr2_kernel<<<(N * 32 + T - 1) / T, T>>>(p_ptr, p_csr, p_as2, p_ad2, p_h2h, b2, out, N);
}